// round 14
// baseline (speedup 1.0000x reference)
#include <cuda_runtime.h>
#include <math.h>
#include <stdint.h>

// Problem constants
#define SIG_LEN   131072
#define NW        4
#define ROWS      256
#define T_OUT     131166
#define SPLIT     8
#define CHK       16384               // input samples owned per block
#define SS        2048                // input samples per scan step

typedef unsigned long long ull;

// ---------------------------------------------------------------------------
__device__ __forceinline__ ull fma2(ull a, ull b, ull c) {
    ull d;
    asm("fma.rn.f32x2 %0, %1, %2, %3;" : "=l"(d) : "l"(a), "l"(b), "l"(c));
    return d;
}
__device__ __forceinline__ float hsum2(ull a) {
    float2 v = *reinterpret_cast<float2*>(&a);
    return v.x + v.y;
}

// Shared-memory arena (floats). Step phase: s_in0, s_in1, s_l1, s_a2.
// Tail phase overlays s_l3/l4/l5 on the s_in region. s_a2 persists.
// Filter-constraint scratch lives transiently inside s_a2 (prologue only).
#define OFF_IN0 0      // 2080 floats
#define OFF_IN1 2080   // 2080 floats
#define OFF_L1  4160   // 1056 floats (15 carry + 1024)
#define OFF_L3  0      // 2208 floats (tail overlay)
#define OFF_L4  2208   // 1120 floats
#define OFF_L5  3328   // 576 floats
#define OFF_A2  5216   // 4656 floats (l2 approx: chunk + halo, +3 shift)
#define ARENA   9872
// prologue scratch (inside s_a2, away from its head pad / tail zero regions)
#define SW (OFF_A2 + 512)   // 66 floats: gaussian weights w[bank][f]
#define SC (SW + 66)        // 62 floats: C[bank][d+15], d in [-15,15]
#define ST (SC + 62)        // 32 floats: raw taps
#define SF (ST + 32)        // 32 floats: final filters [lp 16 | hp 16]

// ---------------------------------------------------------------------------
// Staging: s_in[i] = x[pin-15+i], i in [0, 2064). CHECK=false -> bare cp.async.
// ---------------------------------------------------------------------------
template<bool CHECK>
__device__ __forceinline__ void stage(uint32_t smb, const float* __restrict__ x,
                                      int off, int pin, int tid)
{
    #pragma unroll
    for (int c = 0; c < 9; c++) {
        int i = tid + 256 * c;
        if (c == 8 && tid >= 16) break;
        int gi = pin - 15 + i;
        uint32_t sa = smb + (uint32_t)(off + i) * 4u;
        if (CHECK) {
            bool ok = (gi >= 0) && (gi < SIG_LEN);
            const float* gp = x + (ok ? gi : 0);
            int sz = ok ? 4 : 0;
            asm volatile("cp.async.ca.shared.global [%0], [%1], 4, %2;"
                         :: "r"(sa), "l"(gp), "r"(sz) : "memory");
        } else {
            const float* gp = x + gi;
            asm volatile("cp.async.ca.shared.global [%0], [%1], 4;"
                         :: "r"(sa), "l"(gp) : "memory");
        }
    }
}

// ---------------------------------------------------------------------------
// Level-1 pass: 1024 outputs, 2/thread x 2 iters. Window q = src[2q..2q+17].
// Approx -> dst[15+q]; detail -> det[q] (float2 when unmasked).
// ---------------------------------------------------------------------------
template<bool DET, bool MASK>
__device__ __forceinline__ void l1_pass(const float* __restrict__ src,
                                        float* __restrict__ dst,
                                        float* __restrict__ det, int hi,
                                        const ull* fa, const ull* fd, int tid)
{
    #pragma unroll
    for (int it = 0; it < 2; it++) {
        const int q = 2 * tid + 512 * it;
        const float* w = src + 2 * q;
        ulonglong2 v0 = *(const ulonglong2*)(w);
        ulonglong2 v1 = *(const ulonglong2*)(w + 4);
        ulonglong2 v2 = *(const ulonglong2*)(w + 8);
        ulonglong2 v3 = *(const ulonglong2*)(w + 12);
        ull p8 = *(const ull*)(w + 16);
        ull P[9] = {v0.x, v0.y, v1.x, v1.y, v2.x, v2.y, v3.x, v3.y, p8};
        ull a0 = 0ull, a1 = 0ull;
        #pragma unroll
        for (int m = 0; m < 8; m++) {
            a0 = fma2(fa[m], P[m],     a0);
            a1 = fma2(fa[m], P[m + 1], a1);
        }
        dst[15 + q] = hsum2(a0);
        dst[16 + q] = hsum2(a1);
        if (DET) {
            ull d0 = 0ull, d1 = 0ull;
            #pragma unroll
            for (int m = 0; m < 8; m++) {
                d0 = fma2(fd[m], P[m],     d0);
                d1 = fma2(fd[m], P[m + 1], d1);
            }
            float rd0 = hsum2(d0), rd1 = hsum2(d1);
            if (!MASK) {
                *reinterpret_cast<float2*>(det + q) = make_float2(rd0, rd1);
            } else {
                if (q < hi)     det[q]     = rd0;
                if (q + 1 < hi) det[q + 1] = rd1;
            }
        }
    }
}

// ---------------------------------------------------------------------------
// Level-2 pass: 512 outputs, 2/thread, one iter. Window q = src[2q..2q+17].
// ---------------------------------------------------------------------------
template<bool DET, bool MASK>
__device__ __forceinline__ void l2_pass(const float* __restrict__ src,
                                        float* __restrict__ a2,
                                        float* __restrict__ det,
                                        int hi, int dqlim,
                                        const ull* fa, const ull* fd, int tid)
{
    const int q = 2 * tid;
    const float* w = src + 2 * q;
    ulonglong2 v0 = *(const ulonglong2*)(w);
    ulonglong2 v1 = *(const ulonglong2*)(w + 4);
    ulonglong2 v2 = *(const ulonglong2*)(w + 8);
    ulonglong2 v3 = *(const ulonglong2*)(w + 12);
    ull p8 = *(const ull*)(w + 16);
    ull P[9] = {v0.x, v0.y, v1.x, v1.y, v2.x, v2.y, v3.x, v3.y, p8};
    ull a0 = 0ull, a1 = 0ull;
    #pragma unroll
    for (int m = 0; m < 8; m++) {
        a0 = fma2(fa[m], P[m],     a0);
        a1 = fma2(fa[m], P[m + 1], a1);
    }
    float ra0 = hsum2(a0), ra1 = hsum2(a1);
    if (!MASK) { a2[q] = ra0; a2[q + 1] = ra1; }
    else {
        if (q < dqlim)     a2[q]     = ra0;
        if (q + 1 < dqlim) a2[q + 1] = ra1;
    }
    if (DET) {
        ull d0 = 0ull, d1 = 0ull;
        #pragma unroll
        for (int m = 0; m < 8; m++) {
            d0 = fma2(fd[m], P[m],     d0);
            d1 = fma2(fd[m], P[m + 1], d1);
        }
        float rd0 = hsum2(d0), rd1 = hsum2(d1);
        if (!MASK) {
            *reinterpret_cast<float2*>(det + q) = make_float2(rd0, rd1);
        } else {
            if (q < hi)     det[q]     = rd0;
            if (q + 1 < hi) det[q + 1] = rd1;
        }
    }
}

// ---------------------------------------------------------------------------
// Fused constraint + 6-level DWT. Grid (SPLIT, ROWS), 256 threads, 4/SM.
// Prologue computes THIS block's two constrained filters in smem scratch
// (overlapped with step-0 cp.async staging):
//   filt[j] = (1/64) sum_k src[k]*C[j-k], C[d] = w0 + 2*sum w_f cos(2pi f d/64)
//             + w32 cos(pi d), then L2-normalize * sqrt2.
// ---------------------------------------------------------------------------
__global__ void __launch_bounds__(256, 4)
fused_dwt_kernel(const float* __restrict__ signal,
                 const float* __restrict__ low,
                 const float* __restrict__ high,
                 float* __restrict__ out)
{
    __shared__ __align__(16) float sm[ARENA];
    const int tid = threadIdx.x;
    const int j   = blockIdx.x;
    const int r   = blockIdx.y;
    const int n   = r & 3;
    const float* x = signal + (size_t)(r >> 2) * SIG_LEN;
    float* orow = out + (size_t)r * T_OUT;

    uint32_t smb;
    asm("{ .reg .u64 t; cvta.to.shared.u64 t, %1; cvt.u32.u64 %0, t; }"
        : "=r"(smb) : "l"(sm));

    const int P0    = j * CHK - SS;
    const int nstep = (j == SPLIT - 1) ? 10 : 9;

    // Kick off step-0 staging FIRST (DRAM fetch overlaps filter math below)
    if (P0 >= 2048) stage<false>(smb, x, OFF_IN0, P0, tid);
    else            stage<true >(smb, x, OFF_IN0, P0, tid);
    asm volatile("cp.async.commit_group;" ::: "memory");

    // ---- In-block filter constraint (this block's wavelet n, lp+hp) ----
    // 1) gaussian weights w[bank][f], f in [0,32]
    if (tid < 66) {
        int bank = (tid >= 33);
        int f    = bank ? tid - 33 : tid;
        float target = ((float)n + 0.5f) * 0.125f + (bank ? 0.5f : 0.0f);
        float d = ((float)f * (1.0f / 32.0f) - target) * 4.0f;
        sm[SW + tid] = expf(-d * d);
    }
    __syncthreads();
    // 2) cosine kernel C[bank][d+15], d = j - k in [-15, 15]
    if (tid < 62) {
        int bank = (tid >= 31);
        int dm   = bank ? tid - 31 : tid;
        int dd   = dm - 15 + 64;                 // positive, same mod 64
        const float* wp = sm + SW + bank * 33;
        float c = wp[0];
        #pragma unroll
        for (int f = 1; f <= 31; f++)
            c = fmaf(2.0f * wp[f],
                     cosf(0.0981747704246810f * (float)((dd * f) & 63)), c);
        c = fmaf(wp[32], cosf(0.0981747704246810f * (float)((dd * 32) & 63)), c);
        sm[SC + tid] = c;
    }
    __syncthreads();
    // 3) raw taps
    if (tid < 32) {
        int bank = (tid >= 16);
        int jt   = bank ? tid - 16 : tid;
        const float* src = (bank ? high : low) + n * 16;
        const float* Cp  = sm + SC + bank * 31;
        float acc = 0.0f;
        #pragma unroll
        for (int k = 0; k < 16; k++)
            acc = fmaf(src[k], Cp[jt - k + 15], acc);
        sm[ST + tid] = acc * (1.0f / 64.0f);
    }
    __syncthreads();
    // 4) L2-normalize * sqrt2
    if (tid < 32) {
        int bank = (tid >= 16);
        const float* tp = sm + ST + bank * 16;
        float ss = 0.0f;
        #pragma unroll
        for (int m = 0; m < 16; m++) ss = fmaf(tp[m], tp[m], ss);
        float nrm = sqrtf(ss);
        if (nrm < 1e-12f) nrm = 1e-12f;
        sm[SF + tid] = sm[ST + tid] / nrm * 1.41421356237309515f;
    }
    __syncthreads();

    // Filters as packed f32x2 in registers (smem broadcast)
    ull fa[8], fd[8];
    {
        const ull* fp = (const ull*)(sm + SF);
        #pragma unroll
        for (int m = 0; m < 8; m++) { fa[m] = fp[m]; fd[m] = fp[m + 8]; }
    }

    // Init zeros: s_l1 tail (first carry source), s_a2 head pad + tail zeros
    if (tid < 15)               sm[OFF_L1 + 1024 + tid] = 0.f;
    if (tid >= 32 && tid < 35)  sm[OFF_A2 + (tid - 32)] = 0.f;
    if (tid >= 64 && tid < 112) sm[OFF_A2 + 4608 + (tid - 64)] = 0.f;

    const int Lout[6] = {65544, 32780, 16398, 8207, 4111, 2063};
    int olo[6], ohi[6];
    #pragma unroll
    for (int l = 0; l < 6; l++) {
        int c = CHK >> (l + 1);
        olo[l] = j * c;
        ohi[l] = (j == SPLIT - 1) ? Lout[l] : (j + 1) * c;
    }
    float* gd1 = orow + 65622;  float* gd2 = orow + 32842;
    float* gd3 = orow + 16444;  float* gd4 = orow + 8237;
    float* gd5 = orow + 4126;   float* gd6 = orow + 2063;

    // Generic masked 2-output level (tail levels 3..6)
    auto level = [&](const float* __restrict__ src, int woff,
                     float* __restrict__ dst, int dst0,
                     float* __restrict__ det, int tg0, int lo, int hi,
                     float* __restrict__ app, int nq)
    {
        for (int q = 2 * tid; q < nq; q += 512) {
            const float* w = src + woff + 2 * q;
            ulonglong2 v0 = *(const ulonglong2*)(w);
            ulonglong2 v1 = *(const ulonglong2*)(w + 4);
            ulonglong2 v2 = *(const ulonglong2*)(w + 8);
            ulonglong2 v3 = *(const ulonglong2*)(w + 12);
            ull p8 = *(const ull*)(w + 16);
            ull P[9] = {v0.x, v0.y, v1.x, v1.y, v2.x, v2.y, v3.x, v3.y, p8};
            ull a0 = 0ull, a1 = 0ull, d0 = 0ull, d1 = 0ull;
            #pragma unroll
            for (int m = 0; m < 8; m++) {
                a0 = fma2(fa[m], P[m],     a0);
                d0 = fma2(fd[m], P[m],     d0);
                a1 = fma2(fa[m], P[m + 1], a1);
                d1 = fma2(fd[m], P[m + 1], d1);
            }
            float ra0 = hsum2(a0), ra1 = hsum2(a1);
            float rd0 = hsum2(d0), rd1 = hsum2(d1);
            if (dst) { dst[dst0 + q] = ra0; dst[dst0 + q + 1] = ra1; }
            const int t = tg0 + q;
            if (t >= lo && t < hi)     { det[t]     = rd0; if (app) app[t]     = ra0; }
            if (t+1 >= lo && t+1 < hi) { det[t + 1] = rd1; if (app) app[t + 1] = ra1; }
        }
    };

    const int base2 = j * 4096 - 512;

    for (int step = 0; step < nstep; step++) {
        const int pin  = P0 + step * SS;
        const int cbuf = (step & 1) ? OFF_IN1 : OFF_IN0;
        const int nbuf = (step & 1) ? OFF_IN0 : OFF_IN1;
        __syncthreads();                         // prev L1/L2 reads done

        // Carry s_l1 head <- old tail; prefetch next step; wait current.
        if (tid < 15) sm[OFF_L1 + tid] = sm[OFF_L1 + 1024 + tid];
        if (step + 1 < nstep) {
            const int np = pin + SS;
            if (np >= 2048 && np < 129024) stage<false>(smb, x, nbuf, np, tid);
            else                           stage<true >(smb, x, nbuf, np, tid);
            asm volatile("cp.async.commit_group;" ::: "memory");
            asm volatile("cp.async.wait_group 1;" ::: "memory");
        } else {
            asm volatile("cp.async.wait_group 0;" ::: "memory");
        }
        __syncthreads();

        // Level 1: 1024 outputs at t = (pin>>1)+q; approx -> s_l1[15+q]
        float* d1p = gd1 + (pin >> 1);
        if (step == 0)
            l1_pass<false, false>(sm + cbuf, sm + OFF_L1, d1p, 0, fa, fd, tid);
        else if (step <= 8)
            l1_pass<true,  false>(sm + cbuf, sm + OFF_L1, d1p, 0, fa, fd, tid);
        else
            l1_pass<true,  true >(sm + cbuf, sm + OFF_L1, d1p,
                                  ohi[0] - (pin >> 1), fa, fd, tid);
        __syncthreads();

        // Level 2: 512 outputs at t = (pin>>2)+q; approx -> s_a2[step*512+3+q]
        float* a2d = sm + OFF_A2 + step * 512 + 3;
        float* d2p = gd2 + (pin >> 2);
        if (step == 0)
            l2_pass<false, false>(sm + OFF_L1, a2d, d2p, 0, 0, fa, fd, tid);
        else if (step <= 8)
            l2_pass<true,  false>(sm + OFF_L1, a2d, d2p, 0, 0, fa, fd, tid);
        else
            l2_pass<true,  true >(sm + OFF_L1, a2d, d2p,
                                  ohi[1] - (pin >> 2),
                                  Lout[1] - (base2 + step * 512), fa, fd, tid);
    }

    __syncthreads();
    // Zero tail-buffer pads (heads [0,3) and right-edge zero regions)
    if (tid < 3) { sm[OFF_L3 + tid] = 0.f; sm[OFF_L4 + tid] = 0.f; sm[OFF_L5 + tid] = 0.f; }
    if (tid >= 32 && tid < 63)  sm[OFF_L3 + 2177 + (tid - 32)] = 0.f;
    if (tid >= 64 && tid < 94)  sm[OFF_L4 + 1090 + (tid - 64)] = 0.f;
    if (tid >= 96 && tid < 126) sm[OFF_L5 +  546 + (tid - 96)] = 0.f;
    __syncthreads();

    // Tail: levels 3..6 once. Left halos 112/48/16 cover the dependency cone.
    {
        const int a3 = olo[2] - 112, n3 = ohi[2] - a3;      // even
        level(sm + OFF_A2, 276, sm + OFF_L3, 3,
              gd3, a3, olo[2], ohi[2], (float*)0, n3);
        __syncthreads();

        const int a4 = olo[3] - 48, n4 = ohi[3] - a4;
        level(sm + OFF_L3, 4, sm + OFF_L4, 3,
              gd4, a4, olo[3], ohi[3], (float*)0, n4);
        __syncthreads();

        const int a5 = olo[4] - 16, n5 = ohi[4] - a5;
        level(sm + OFF_L4, 4, sm + OFF_L5, 3,
              gd5, a5, olo[4], ohi[4], (float*)0, n5);
        __syncthreads();

        level(sm + OFF_L5, 4, (float*)0, 0,
              gd6, olo[5], olo[5], ohi[5], orow, ohi[5] - olo[5]);
    }
}

// ---------------------------------------------------------------------------
extern "C" void kernel_launch(void* const* d_in, const int* in_sizes, int n_in,
                              void* d_out, int out_size) {
    const float* signal = (const float*)d_in[0];
    const float* low    = (const float*)d_in[1];
    const float* high   = (const float*)d_in[2];
    float* out = (float*)d_out;

    dim3 grid(SPLIT, ROWS);
    fused_dwt_kernel<<<grid, 256>>>(signal, low, high, out);
}

// round 15
// speedup vs baseline: 1.0613x; 1.0613x over previous
#include <cuda_runtime.h>
#include <math.h>
#include <stdint.h>

// Problem constants
#define SIG_LEN   131072
#define NW        4
#define ROWS      256
#define T_OUT     131166
#define SPLIT     8
#define CHK       16384               // input samples owned per block
#define SS        2048                // input samples per scan step

typedef unsigned long long ull;

// Host-computed constraint table: C[bank*4+n][d+15] includes the 1/64 factor.
struct FiltTab { float C[8][31]; };

// ---------------------------------------------------------------------------
__device__ __forceinline__ ull fma2(ull a, ull b, ull c) {
    ull d;
    asm("fma.rn.f32x2 %0, %1, %2, %3;" : "=l"(d) : "l"(a), "l"(b), "l"(c));
    return d;
}
__device__ __forceinline__ float hsum2(ull a) {
    float2 v = *reinterpret_cast<float2*>(&a);
    return v.x + v.y;
}

// Shared-memory arena (floats). Step phase: s_in0, s_in1, s_l1, s_a2.
// Tail phase overlays s_l3/l4/l5 on the s_in region. s_a2 persists.
#define OFF_IN0 0      // 2080 floats
#define OFF_IN1 2080   // 2080 floats
#define OFF_L1  4160   // 1056 floats (15 carry + 1024); prologue scratch early
#define OFF_L3  0      // 2208 floats (tail overlay)
#define OFF_L4  2208   // 1120 floats
#define OFF_L5  3328   // 576 floats
#define OFF_A2  5216   // 4656 floats (l2 approx: chunk + halo, +3 shift)
#define ARENA   9872

// ---------------------------------------------------------------------------
// Staging: s_in[i] = x[pin-15+i], i in [0, 2064). CHECK=false -> bare cp.async.
// ---------------------------------------------------------------------------
template<bool CHECK>
__device__ __forceinline__ void stage(uint32_t smb, const float* __restrict__ x,
                                      int off, int pin, int tid)
{
    #pragma unroll
    for (int c = 0; c < 9; c++) {
        int i = tid + 256 * c;
        if (c == 8 && tid >= 16) break;
        int gi = pin - 15 + i;
        uint32_t sa = smb + (uint32_t)(off + i) * 4u;
        if (CHECK) {
            bool ok = (gi >= 0) && (gi < SIG_LEN);
            const float* gp = x + (ok ? gi : 0);
            int sz = ok ? 4 : 0;
            asm volatile("cp.async.ca.shared.global [%0], [%1], 4, %2;"
                         :: "r"(sa), "l"(gp), "r"(sz) : "memory");
        } else {
            const float* gp = x + gi;
            asm volatile("cp.async.ca.shared.global [%0], [%1], 4;"
                         :: "r"(sa), "l"(gp) : "memory");
        }
    }
}

// ---------------------------------------------------------------------------
// Level-1 pass: 1024 outputs, 2/thread x 2 iters. Window q = src[2q..2q+17].
// Approx -> dst[15+q]; detail -> det[q] (float2 when unmasked).
// ---------------------------------------------------------------------------
template<bool DET, bool MASK>
__device__ __forceinline__ void l1_pass(const float* __restrict__ src,
                                        float* __restrict__ dst,
                                        float* __restrict__ det, int hi,
                                        const ull* fa, const ull* fd, int tid)
{
    #pragma unroll
    for (int it = 0; it < 2; it++) {
        const int q = 2 * tid + 512 * it;
        const float* w = src + 2 * q;
        ulonglong2 v0 = *(const ulonglong2*)(w);
        ulonglong2 v1 = *(const ulonglong2*)(w + 4);
        ulonglong2 v2 = *(const ulonglong2*)(w + 8);
        ulonglong2 v3 = *(const ulonglong2*)(w + 12);
        ull p8 = *(const ull*)(w + 16);
        ull P[9] = {v0.x, v0.y, v1.x, v1.y, v2.x, v2.y, v3.x, v3.y, p8};
        ull a0 = 0ull, a1 = 0ull;
        #pragma unroll
        for (int m = 0; m < 8; m++) {
            a0 = fma2(fa[m], P[m],     a0);
            a1 = fma2(fa[m], P[m + 1], a1);
        }
        dst[15 + q] = hsum2(a0);
        dst[16 + q] = hsum2(a1);
        if (DET) {
            ull d0 = 0ull, d1 = 0ull;
            #pragma unroll
            for (int m = 0; m < 8; m++) {
                d0 = fma2(fd[m], P[m],     d0);
                d1 = fma2(fd[m], P[m + 1], d1);
            }
            float rd0 = hsum2(d0), rd1 = hsum2(d1);
            if (!MASK) {
                *reinterpret_cast<float2*>(det + q) = make_float2(rd0, rd1);
            } else {
                if (q < hi)     det[q]     = rd0;
                if (q + 1 < hi) det[q + 1] = rd1;
            }
        }
    }
}

// ---------------------------------------------------------------------------
// Level-2 pass: 512 outputs, 2/thread, one iter. Window q = src[2q..2q+17].
// ---------------------------------------------------------------------------
template<bool DET, bool MASK>
__device__ __forceinline__ void l2_pass(const float* __restrict__ src,
                                        float* __restrict__ a2,
                                        float* __restrict__ det,
                                        int hi, int dqlim,
                                        const ull* fa, const ull* fd, int tid)
{
    const int q = 2 * tid;
    const float* w = src + 2 * q;
    ulonglong2 v0 = *(const ulonglong2*)(w);
    ulonglong2 v1 = *(const ulonglong2*)(w + 4);
    ulonglong2 v2 = *(const ulonglong2*)(w + 8);
    ulonglong2 v3 = *(const ulonglong2*)(w + 12);
    ull p8 = *(const ull*)(w + 16);
    ull P[9] = {v0.x, v0.y, v1.x, v1.y, v2.x, v2.y, v3.x, v3.y, p8};
    ull a0 = 0ull, a1 = 0ull;
    #pragma unroll
    for (int m = 0; m < 8; m++) {
        a0 = fma2(fa[m], P[m],     a0);
        a1 = fma2(fa[m], P[m + 1], a1);
    }
    float ra0 = hsum2(a0), ra1 = hsum2(a1);
    if (!MASK) { a2[q] = ra0; a2[q + 1] = ra1; }
    else {
        if (q < dqlim)     a2[q]     = ra0;
        if (q + 1 < dqlim) a2[q + 1] = ra1;
    }
    if (DET) {
        ull d0 = 0ull, d1 = 0ull;
        #pragma unroll
        for (int m = 0; m < 8; m++) {
            d0 = fma2(fd[m], P[m],     d0);
            d1 = fma2(fd[m], P[m + 1], d1);
        }
        float rd0 = hsum2(d0), rd1 = hsum2(d1);
        if (!MASK) {
            *reinterpret_cast<float2*>(det + q) = make_float2(rd0, rd1);
        } else {
            if (q < hi)     det[q]     = rd0;
            if (q + 1 < hi) det[q + 1] = rd1;
        }
    }
}

// ---------------------------------------------------------------------------
// Fused constraint + 6-level DWT. Grid (SPLIT, ROWS), 256 threads, 4/SM.
// Prologue (overlapped with step-0 cp.async): taps[j] = sum_k src[k]*C[j-k]
// (C from host param table, 1/64 folded in), then L2-normalize * sqrt2.
// ---------------------------------------------------------------------------
__global__ void __launch_bounds__(256, 4)
fused_dwt_kernel(const float* __restrict__ signal,
                 const float* __restrict__ low,
                 const float* __restrict__ high,
                 float* __restrict__ out,
                 const FiltTab tab)
{
    __shared__ __align__(16) float sm[ARENA];
    const int tid = threadIdx.x;
    const int j   = blockIdx.x;
    const int r   = blockIdx.y;
    const int n   = r & 3;
    const float* x = signal + (size_t)(r >> 2) * SIG_LEN;
    float* orow = out + (size_t)r * T_OUT;

    uint32_t smb;
    asm("{ .reg .u64 t; cvta.to.shared.u64 t, %1; cvt.u32.u64 %0, t; }"
        : "=r"(smb) : "l"(sm));

    const int P0    = j * CHK - SS;
    const int nstep = (j == SPLIT - 1) ? 10 : 9;

    // Kick off step-0 staging FIRST (DRAM fetch overlaps prologue below)
    if (P0 >= 2048) stage<false>(smb, x, OFF_IN0, P0, tid);
    else            stage<true >(smb, x, OFF_IN0, P0, tid);
    asm volatile("cp.async.commit_group;" ::: "memory");

    // ---- Cheap in-block filter constraint (scratch in s_l1 region) ----
    if (tid < 32) {
        int bank = tid >> 4;
        int jt   = tid & 15;
        const float* src = (bank ? high : low) + n * 16;
        const float* Cp  = tab.C[bank * 4 + n];
        float acc = 0.0f;
        #pragma unroll
        for (int k = 0; k < 16; k++)
            acc = fmaf(src[k], Cp[jt - k + 15], acc);
        sm[OFF_L1 + tid] = acc;                  // raw taps (1/64 folded)
    }
    __syncthreads();
    if (tid < 32) {
        int bank = tid >> 4;
        const float* tp = sm + OFF_L1 + bank * 16;
        float ss = 0.0f;
        #pragma unroll
        for (int m = 0; m < 16; m++) ss = fmaf(tp[m], tp[m], ss);
        float nrm = sqrtf(ss);
        if (nrm < 1e-12f) nrm = 1e-12f;
        sm[OFF_L1 + 32 + tid] = sm[OFF_L1 + tid] / nrm * 1.41421356237309515f;
    }
    __syncthreads();

    // Filters as packed f32x2 in registers (smem broadcast)
    ull fa[8], fd[8];
    {
        const ull* fp = (const ull*)(sm + OFF_L1 + 32);
        #pragma unroll
        for (int m = 0; m < 8; m++) { fa[m] = fp[m]; fd[m] = fp[m + 8]; }
    }
    __syncthreads();                             // scratch reads done

    // Init zeros: s_l1 tail (first carry source), s_a2 head pad + tail zeros
    if (tid < 15)               sm[OFF_L1 + 1024 + tid] = 0.f;
    if (tid >= 32 && tid < 35)  sm[OFF_A2 + (tid - 32)] = 0.f;
    if (tid >= 64 && tid < 112) sm[OFF_A2 + 4608 + (tid - 64)] = 0.f;

    const int Lout[6] = {65544, 32780, 16398, 8207, 4111, 2063};
    int olo[6], ohi[6];
    #pragma unroll
    for (int l = 0; l < 6; l++) {
        int c = CHK >> (l + 1);
        olo[l] = j * c;
        ohi[l] = (j == SPLIT - 1) ? Lout[l] : (j + 1) * c;
    }
    float* gd1 = orow + 65622;  float* gd2 = orow + 32842;
    float* gd3 = orow + 16444;  float* gd4 = orow + 8237;
    float* gd5 = orow + 4126;   float* gd6 = orow + 2063;

    // Generic masked 2-output level (tail levels 3..6)
    auto level = [&](const float* __restrict__ src, int woff,
                     float* __restrict__ dst, int dst0,
                     float* __restrict__ det, int tg0, int lo, int hi,
                     float* __restrict__ app, int nq)
    {
        for (int q = 2 * tid; q < nq; q += 512) {
            const float* w = src + woff + 2 * q;
            ulonglong2 v0 = *(const ulonglong2*)(w);
            ulonglong2 v1 = *(const ulonglong2*)(w + 4);
            ulonglong2 v2 = *(const ulonglong2*)(w + 8);
            ulonglong2 v3 = *(const ulonglong2*)(w + 12);
            ull p8 = *(const ull*)(w + 16);
            ull P[9] = {v0.x, v0.y, v1.x, v1.y, v2.x, v2.y, v3.x, v3.y, p8};
            ull a0 = 0ull, a1 = 0ull, d0 = 0ull, d1 = 0ull;
            #pragma unroll
            for (int m = 0; m < 8; m++) {
                a0 = fma2(fa[m], P[m],     a0);
                d0 = fma2(fd[m], P[m],     d0);
                a1 = fma2(fa[m], P[m + 1], a1);
                d1 = fma2(fd[m], P[m + 1], d1);
            }
            float ra0 = hsum2(a0), ra1 = hsum2(a1);
            float rd0 = hsum2(d0), rd1 = hsum2(d1);
            if (dst) { dst[dst0 + q] = ra0; dst[dst0 + q + 1] = ra1; }
            const int t = tg0 + q;
            if (t >= lo && t < hi)     { det[t]     = rd0; if (app) app[t]     = ra0; }
            if (t+1 >= lo && t+1 < hi) { det[t + 1] = rd1; if (app) app[t + 1] = ra1; }
        }
    };

    const int base2 = j * 4096 - 512;

    for (int step = 0; step < nstep; step++) {
        const int pin  = P0 + step * SS;
        const int cbuf = (step & 1) ? OFF_IN1 : OFF_IN0;
        const int nbuf = (step & 1) ? OFF_IN0 : OFF_IN1;
        __syncthreads();                         // prev L1/L2 reads done

        // Carry s_l1 head <- old tail; prefetch next step; wait current.
        if (tid < 15) sm[OFF_L1 + tid] = sm[OFF_L1 + 1024 + tid];
        if (step + 1 < nstep) {
            const int np = pin + SS;
            if (np >= 2048 && np < 129024) stage<false>(smb, x, nbuf, np, tid);
            else                           stage<true >(smb, x, nbuf, np, tid);
            asm volatile("cp.async.commit_group;" ::: "memory");
            asm volatile("cp.async.wait_group 1;" ::: "memory");
        } else {
            asm volatile("cp.async.wait_group 0;" ::: "memory");
        }
        __syncthreads();

        // Level 1: 1024 outputs at t = (pin>>1)+q; approx -> s_l1[15+q]
        float* d1p = gd1 + (pin >> 1);
        if (step == 0)
            l1_pass<false, false>(sm + cbuf, sm + OFF_L1, d1p, 0, fa, fd, tid);
        else if (step <= 8)
            l1_pass<true,  false>(sm + cbuf, sm + OFF_L1, d1p, 0, fa, fd, tid);
        else
            l1_pass<true,  true >(sm + cbuf, sm + OFF_L1, d1p,
                                  ohi[0] - (pin >> 1), fa, fd, tid);
        __syncthreads();

        // Level 2: 512 outputs at t = (pin>>2)+q; approx -> s_a2[step*512+3+q]
        float* a2d = sm + OFF_A2 + step * 512 + 3;
        float* d2p = gd2 + (pin >> 2);
        if (step == 0)
            l2_pass<false, false>(sm + OFF_L1, a2d, d2p, 0, 0, fa, fd, tid);
        else if (step <= 8)
            l2_pass<true,  false>(sm + OFF_L1, a2d, d2p, 0, 0, fa, fd, tid);
        else
            l2_pass<true,  true >(sm + OFF_L1, a2d, d2p,
                                  ohi[1] - (pin >> 2),
                                  Lout[1] - (base2 + step * 512), fa, fd, tid);
    }

    __syncthreads();
    // Zero tail-buffer pads (heads [0,3) and right-edge zero regions)
    if (tid < 3) { sm[OFF_L3 + tid] = 0.f; sm[OFF_L4 + tid] = 0.f; sm[OFF_L5 + tid] = 0.f; }
    if (tid >= 32 && tid < 63)  sm[OFF_L3 + 2177 + (tid - 32)] = 0.f;
    if (tid >= 64 && tid < 94)  sm[OFF_L4 + 1090 + (tid - 64)] = 0.f;
    if (tid >= 96 && tid < 126) sm[OFF_L5 +  546 + (tid - 96)] = 0.f;
    __syncthreads();

    // Tail: levels 3..6 once. Left halos 112/48/16 cover the dependency cone.
    {
        const int a3 = olo[2] - 112, n3 = ohi[2] - a3;      // even
        level(sm + OFF_A2, 276, sm + OFF_L3, 3,
              gd3, a3, olo[2], ohi[2], (float*)0, n3);
        __syncthreads();

        const int a4 = olo[3] - 48, n4 = ohi[3] - a4;
        level(sm + OFF_L3, 4, sm + OFF_L4, 3,
              gd4, a4, olo[3], ohi[3], (float*)0, n4);
        __syncthreads();

        const int a5 = olo[4] - 16, n5 = ohi[4] - a5;
        level(sm + OFF_L4, 4, sm + OFF_L5, 3,
              gd5, a5, olo[4], ohi[4], (float*)0, n5);
        __syncthreads();

        level(sm + OFF_L5, 4, (float*)0, 0,
              gd6, olo[5], olo[5], ohi[5], orow, ohi[5] - olo[5]);
    }
}

// ---------------------------------------------------------------------------
extern "C" void kernel_launch(void* const* d_in, const int* in_sizes, int n_in,
                              void* d_out, int out_size) {
    const float* signal = (const float*)d_in[0];
    const float* low    = (const float*)d_in[1];
    const float* high   = (const float*)d_in[2];
    float* out = (float*)d_out;

    // Data-independent constraint table, computed on host (double precision):
    // C[d] = (1/64)(w0 + 2*sum_{f=1..31} w_f cos(pi f d/32) + w32 cos(pi d)),
    // w_f = exp(-(((f/32) - target)*4)^2), target = (n+0.5)/8 + bank/2.
    FiltTab tab;
    for (int bank = 0; bank < 2; bank++) {
        for (int nn = 0; nn < 4; nn++) {
            double target = ((double)nn + 0.5) / 8.0 + (bank ? 0.5 : 0.0);
            double w[33];
            for (int f = 0; f <= 32; f++) {
                double d = ((double)f / 32.0 - target) * 4.0;
                w[f] = exp(-d * d);
            }
            for (int d = -15; d <= 15; d++) {
                double c = w[0];
                for (int f = 1; f <= 31; f++)
                    c += 2.0 * w[f] * cos(M_PI * (double)(f * d) / 32.0);
                c += w[32] * cos(M_PI * (double)d);
                tab.C[bank * 4 + nn][d + 15] = (float)(c / 64.0);
            }
        }
    }

    dim3 grid(SPLIT, ROWS);
    fused_dwt_kernel<<<grid, 256>>>(signal, low, high, out, tab);
}

// round 16
// speedup vs baseline: 1.0645x; 1.0030x over previous
#include <cuda_runtime.h>
#include <math.h>
#include <stdint.h>

// Problem constants
#define SIG_LEN   131072
#define NW        4
#define ROWS      256
#define T_OUT     131166
#define SPLIT     8
#define CHK       16384               // input samples owned per block
#define SS        2048                // input samples per scan step

typedef unsigned long long ull;

// Host-computed constraint table: C[bank*4+n][d+15] includes the 1/64 factor.
struct FiltTab { float C[8][31]; };

// ---------------------------------------------------------------------------
__device__ __forceinline__ ull fma2(ull a, ull b, ull c) {
    ull d;
    asm("fma.rn.f32x2 %0, %1, %2, %3;" : "=l"(d) : "l"(a), "l"(b), "l"(c));
    return d;
}
__device__ __forceinline__ float hsum2(ull a) {
    float2 v = *reinterpret_cast<float2*>(&a);
    return v.x + v.y;
}

// Shared-memory arena (floats). Step phase: s_in0, s_in1, s_l1, s_a2.
// Tail phase overlays s_l3/l4/l5 on the s_in region. s_a2 persists.
#define OFF_IN0 0      // 2080 floats
#define OFF_IN1 2080   // 2080 floats
#define OFF_L1  4160   // 1056 floats (15 carry + 1024)
#define OFF_L3  0      // 2208 floats (tail overlay)
#define OFF_L4  2208   // 1120 floats
#define OFF_L5  3328   // 576 floats
#define OFF_A2  5216   // 4656 floats (l2 approx: chunk + halo, +3 shift)
#define ARENA   9872
// filter scratch: inside s_a2, away from zero-init regions; consumed into
// registers at kernel start, overwritten harmlessly by l2_pass later.
#define SFILT   (OFF_A2 + 2000)

// ---------------------------------------------------------------------------
// Staging: s_in[i] = x[pin-15+i], i in [0, 2064). CHECK=false -> bare cp.async.
// ---------------------------------------------------------------------------
template<bool CHECK>
__device__ __forceinline__ void stage(uint32_t smb, const float* __restrict__ x,
                                      int off, int pin, int tid)
{
    #pragma unroll
    for (int c = 0; c < 9; c++) {
        int i = tid + 256 * c;
        if (c == 8 && tid >= 16) break;
        int gi = pin - 15 + i;
        uint32_t sa = smb + (uint32_t)(off + i) * 4u;
        if (CHECK) {
            bool ok = (gi >= 0) && (gi < SIG_LEN);
            const float* gp = x + (ok ? gi : 0);
            int sz = ok ? 4 : 0;
            asm volatile("cp.async.ca.shared.global [%0], [%1], 4, %2;"
                         :: "r"(sa), "l"(gp), "r"(sz) : "memory");
        } else {
            const float* gp = x + gi;
            asm volatile("cp.async.ca.shared.global [%0], [%1], 4;"
                         :: "r"(sa), "l"(gp) : "memory");
        }
    }
}

// ---------------------------------------------------------------------------
// Level-1 pass: 1024 outputs, 2/thread x 2 iters. Window q = src[2q..2q+17].
// Approx -> dst[15+q]; detail -> det[q] (float2 when unmasked).
// ---------------------------------------------------------------------------
template<bool DET, bool MASK>
__device__ __forceinline__ void l1_pass(const float* __restrict__ src,
                                        float* __restrict__ dst,
                                        float* __restrict__ det, int hi,
                                        const ull* fa, const ull* fd, int tid)
{
    #pragma unroll
    for (int it = 0; it < 2; it++) {
        const int q = 2 * tid + 512 * it;
        const float* w = src + 2 * q;
        ulonglong2 v0 = *(const ulonglong2*)(w);
        ulonglong2 v1 = *(const ulonglong2*)(w + 4);
        ulonglong2 v2 = *(const ulonglong2*)(w + 8);
        ulonglong2 v3 = *(const ulonglong2*)(w + 12);
        ull p8 = *(const ull*)(w + 16);
        ull P[9] = {v0.x, v0.y, v1.x, v1.y, v2.x, v2.y, v3.x, v3.y, p8};
        ull a0 = 0ull, a1 = 0ull;
        #pragma unroll
        for (int m = 0; m < 8; m++) {
            a0 = fma2(fa[m], P[m],     a0);
            a1 = fma2(fa[m], P[m + 1], a1);
        }
        dst[15 + q] = hsum2(a0);
        dst[16 + q] = hsum2(a1);
        if (DET) {
            ull d0 = 0ull, d1 = 0ull;
            #pragma unroll
            for (int m = 0; m < 8; m++) {
                d0 = fma2(fd[m], P[m],     d0);
                d1 = fma2(fd[m], P[m + 1], d1);
            }
            float rd0 = hsum2(d0), rd1 = hsum2(d1);
            if (!MASK) {
                *reinterpret_cast<float2*>(det + q) = make_float2(rd0, rd1);
            } else {
                if (q < hi)     det[q]     = rd0;
                if (q + 1 < hi) det[q + 1] = rd1;
            }
        }
    }
}

// ---------------------------------------------------------------------------
// Level-2 pass: 512 outputs, 2/thread, one iter. Window q = src[2q..2q+17].
// ---------------------------------------------------------------------------
template<bool DET, bool MASK>
__device__ __forceinline__ void l2_pass(const float* __restrict__ src,
                                        float* __restrict__ a2,
                                        float* __restrict__ det,
                                        int hi, int dqlim,
                                        const ull* fa, const ull* fd, int tid)
{
    const int q = 2 * tid;
    const float* w = src + 2 * q;
    ulonglong2 v0 = *(const ulonglong2*)(w);
    ulonglong2 v1 = *(const ulonglong2*)(w + 4);
    ulonglong2 v2 = *(const ulonglong2*)(w + 8);
    ulonglong2 v3 = *(const ulonglong2*)(w + 12);
    ull p8 = *(const ull*)(w + 16);
    ull P[9] = {v0.x, v0.y, v1.x, v1.y, v2.x, v2.y, v3.x, v3.y, p8};
    ull a0 = 0ull, a1 = 0ull;
    #pragma unroll
    for (int m = 0; m < 8; m++) {
        a0 = fma2(fa[m], P[m],     a0);
        a1 = fma2(fa[m], P[m + 1], a1);
    }
    float ra0 = hsum2(a0), ra1 = hsum2(a1);
    if (!MASK) { a2[q] = ra0; a2[q + 1] = ra1; }
    else {
        if (q < dqlim)     a2[q]     = ra0;
        if (q + 1 < dqlim) a2[q + 1] = ra1;
    }
    if (DET) {
        ull d0 = 0ull, d1 = 0ull;
        #pragma unroll
        for (int m = 0; m < 8; m++) {
            d0 = fma2(fd[m], P[m],     d0);
            d1 = fma2(fd[m], P[m + 1], d1);
        }
        float rd0 = hsum2(d0), rd1 = hsum2(d1);
        if (!MASK) {
            *reinterpret_cast<float2*>(det + q) = make_float2(rd0, rd1);
        } else {
            if (q < hi)     det[q]     = rd0;
            if (q + 1 < hi) det[q + 1] = rd1;
        }
    }
}

// ---------------------------------------------------------------------------
// Fused constraint + 6-level DWT. Grid (SPLIT, ROWS), 256 threads, 4/SM.
// Prologue: warp 0 computes taps[j] = sum_k src[k]*C[j-k] (C host table,
// 1/64 folded), shfl-reduces the L2 norm within each 16-lane bank, stores
// the 32 final filter floats; ONE barrier publishes them. Overlaps the
// already-issued step-0 cp.async DRAM fetch.
// ---------------------------------------------------------------------------
__global__ void __launch_bounds__(256, 4)
fused_dwt_kernel(const float* __restrict__ signal,
                 const float* __restrict__ low,
                 const float* __restrict__ high,
                 float* __restrict__ out,
                 const FiltTab tab)
{
    __shared__ __align__(16) float sm[ARENA];
    const int tid = threadIdx.x;
    const int j   = blockIdx.x;
    const int r   = blockIdx.y;
    const int n   = r & 3;
    const float* x = signal + (size_t)(r >> 2) * SIG_LEN;
    float* orow = out + (size_t)r * T_OUT;

    uint32_t smb;
    asm("{ .reg .u64 t; cvta.to.shared.u64 t, %1; cvt.u32.u64 %0, t; }"
        : "=r"(smb) : "l"(sm));

    const int P0    = j * CHK - SS;
    const int nstep = (j == SPLIT - 1) ? 10 : 9;

    // Kick off step-0 staging FIRST (DRAM fetch overlaps prologue below)
    if (P0 >= 2048) stage<false>(smb, x, OFF_IN0, P0, tid);
    else            stage<true >(smb, x, OFF_IN0, P0, tid);
    asm volatile("cp.async.commit_group;" ::: "memory");

    // ---- Warp-0 filter constraint (no intermediate barriers) ----
    if (tid < 32) {
        const int bank = tid >> 4;
        const int jt   = tid & 15;
        const float* src = (bank ? high : low) + n * 16;
        const float* Cp  = tab.C[bank * 4 + n];
        float acc = 0.0f;
        #pragma unroll
        for (int k = 0; k < 16; k++)
            acc = fmaf(src[k], Cp[jt - k + 15], acc);
        float ss = acc * acc;
        #pragma unroll
        for (int m = 8; m >= 1; m >>= 1)
            ss += __shfl_xor_sync(0xffffffffu, ss, m);
        float nrm = sqrtf(ss);
        if (nrm < 1e-12f) nrm = 1e-12f;
        sm[SFILT + tid] = acc / nrm * 1.41421356237309515f;
    }

    // Init zeros: s_l1 tail (first carry source), s_a2 head pad + tail zeros
    if (tid < 15)               sm[OFF_L1 + 1024 + tid] = 0.f;
    if (tid >= 32 && tid < 35)  sm[OFF_A2 + (tid - 32)] = 0.f;
    if (tid >= 64 && tid < 112) sm[OFF_A2 + 4608 + (tid - 64)] = 0.f;
    __syncthreads();                             // publish filters + zeros

    // Filters as packed f32x2 in registers (smem broadcast)
    ull fa[8], fd[8];
    {
        const ull* fp = (const ull*)(sm + SFILT);
        #pragma unroll
        for (int m = 0; m < 8; m++) { fa[m] = fp[m]; fd[m] = fp[m + 8]; }
    }

    const int Lout[6] = {65544, 32780, 16398, 8207, 4111, 2063};
    int olo[6], ohi[6];
    #pragma unroll
    for (int l = 0; l < 6; l++) {
        int c = CHK >> (l + 1);
        olo[l] = j * c;
        ohi[l] = (j == SPLIT - 1) ? Lout[l] : (j + 1) * c;
    }
    float* gd1 = orow + 65622;  float* gd2 = orow + 32842;
    float* gd3 = orow + 16444;  float* gd4 = orow + 8237;
    float* gd5 = orow + 4126;   float* gd6 = orow + 2063;

    // Generic masked 2-output level (tail levels 3..6)
    auto level = [&](const float* __restrict__ src, int woff,
                     float* __restrict__ dst, int dst0,
                     float* __restrict__ det, int tg0, int lo, int hi,
                     float* __restrict__ app, int nq)
    {
        for (int q = 2 * tid; q < nq; q += 512) {
            const float* w = src + woff + 2 * q;
            ulonglong2 v0 = *(const ulonglong2*)(w);
            ulonglong2 v1 = *(const ulonglong2*)(w + 4);
            ulonglong2 v2 = *(const ulonglong2*)(w + 8);
            ulonglong2 v3 = *(const ulonglong2*)(w + 12);
            ull p8 = *(const ull*)(w + 16);
            ull P[9] = {v0.x, v0.y, v1.x, v1.y, v2.x, v2.y, v3.x, v3.y, p8};
            ull a0 = 0ull, a1 = 0ull, d0 = 0ull, d1 = 0ull;
            #pragma unroll
            for (int m = 0; m < 8; m++) {
                a0 = fma2(fa[m], P[m],     a0);
                d0 = fma2(fd[m], P[m],     d0);
                a1 = fma2(fa[m], P[m + 1], a1);
                d1 = fma2(fd[m], P[m + 1], d1);
            }
            float ra0 = hsum2(a0), ra1 = hsum2(a1);
            float rd0 = hsum2(d0), rd1 = hsum2(d1);
            if (dst) { dst[dst0 + q] = ra0; dst[dst0 + q + 1] = ra1; }
            const int t = tg0 + q;
            if (t >= lo && t < hi)     { det[t]     = rd0; if (app) app[t]     = ra0; }
            if (t+1 >= lo && t+1 < hi) { det[t + 1] = rd1; if (app) app[t + 1] = ra1; }
        }
    };

    const int base2 = j * 4096 - 512;

    for (int step = 0; step < nstep; step++) {
        const int pin  = P0 + step * SS;
        const int cbuf = (step & 1) ? OFF_IN1 : OFF_IN0;
        const int nbuf = (step & 1) ? OFF_IN0 : OFF_IN1;
        __syncthreads();                         // prev L1/L2 reads done

        // Carry s_l1 head <- old tail; prefetch next step; wait current.
        if (tid < 15) sm[OFF_L1 + tid] = sm[OFF_L1 + 1024 + tid];
        if (step + 1 < nstep) {
            const int np = pin + SS;
            if (np >= 2048 && np < 129024) stage<false>(smb, x, nbuf, np, tid);
            else                           stage<true >(smb, x, nbuf, np, tid);
            asm volatile("cp.async.commit_group;" ::: "memory");
            asm volatile("cp.async.wait_group 1;" ::: "memory");
        } else {
            asm volatile("cp.async.wait_group 0;" ::: "memory");
        }
        __syncthreads();

        // Level 1: 1024 outputs at t = (pin>>1)+q; approx -> s_l1[15+q]
        float* d1p = gd1 + (pin >> 1);
        if (step == 0)
            l1_pass<false, false>(sm + cbuf, sm + OFF_L1, d1p, 0, fa, fd, tid);
        else if (step <= 8)
            l1_pass<true,  false>(sm + cbuf, sm + OFF_L1, d1p, 0, fa, fd, tid);
        else
            l1_pass<true,  true >(sm + cbuf, sm + OFF_L1, d1p,
                                  ohi[0] - (pin >> 1), fa, fd, tid);
        __syncthreads();

        // Level 2: 512 outputs at t = (pin>>2)+q; approx -> s_a2[step*512+3+q]
        float* a2d = sm + OFF_A2 + step * 512 + 3;
        float* d2p = gd2 + (pin >> 2);
        if (step == 0)
            l2_pass<false, false>(sm + OFF_L1, a2d, d2p, 0, 0, fa, fd, tid);
        else if (step <= 8)
            l2_pass<true,  false>(sm + OFF_L1, a2d, d2p, 0, 0, fa, fd, tid);
        else
            l2_pass<true,  true >(sm + OFF_L1, a2d, d2p,
                                  ohi[1] - (pin >> 2),
                                  Lout[1] - (base2 + step * 512), fa, fd, tid);
    }

    __syncthreads();
    // Zero tail-buffer pads (heads [0,3) and right-edge zero regions)
    if (tid < 3) { sm[OFF_L3 + tid] = 0.f; sm[OFF_L4 + tid] = 0.f; sm[OFF_L5 + tid] = 0.f; }
    if (tid >= 32 && tid < 63)  sm[OFF_L3 + 2177 + (tid - 32)] = 0.f;
    if (tid >= 64 && tid < 94)  sm[OFF_L4 + 1090 + (tid - 64)] = 0.f;
    if (tid >= 96 && tid < 126) sm[OFF_L5 +  546 + (tid - 96)] = 0.f;
    __syncthreads();

    // Tail: levels 3..6 once. Left halos 112/48/16 cover the dependency cone.
    {
        const int a3 = olo[2] - 112, n3 = ohi[2] - a3;      // even
        level(sm + OFF_A2, 276, sm + OFF_L3, 3,
              gd3, a3, olo[2], ohi[2], (float*)0, n3);
        __syncthreads();

        const int a4 = olo[3] - 48, n4 = ohi[3] - a4;
        level(sm + OFF_L3, 4, sm + OFF_L4, 3,
              gd4, a4, olo[3], ohi[3], (float*)0, n4);
        __syncthreads();

        const int a5 = olo[4] - 16, n5 = ohi[4] - a5;
        level(sm + OFF_L4, 4, sm + OFF_L5, 3,
              gd5, a5, olo[4], ohi[4], (float*)0, n5);
        __syncthreads();

        level(sm + OFF_L5, 4, (float*)0, 0,
              gd6, olo[5], olo[5], ohi[5], orow, ohi[5] - olo[5]);
    }
}

// ---------------------------------------------------------------------------
extern "C" void kernel_launch(void* const* d_in, const int* in_sizes, int n_in,
                              void* d_out, int out_size) {
    const float* signal = (const float*)d_in[0];
    const float* low    = (const float*)d_in[1];
    const float* high   = (const float*)d_in[2];
    float* out = (float*)d_out;

    // Data-independent constraint table, computed on host (double precision):
    // C[d] = (1/64)(w0 + 2*sum_{f=1..31} w_f cos(pi f d/32) + w32 cos(pi d)),
    // w_f = exp(-(((f/32) - target)*4)^2), target = (n+0.5)/8 + bank/2.
    FiltTab tab;
    for (int bank = 0; bank < 2; bank++) {
        for (int nn = 0; nn < 4; nn++) {
            double target = ((double)nn + 0.5) / 8.0 + (bank ? 0.5 : 0.0);
            double w[33];
            for (int f = 0; f <= 32; f++) {
                double d = ((double)f / 32.0 - target) * 4.0;
                w[f] = exp(-d * d);
            }
            for (int d = -15; d <= 15; d++) {
                double c = w[0];
                for (int f = 1; f <= 31; f++)
                    c += 2.0 * w[f] * cos(M_PI * (double)(f * d) / 32.0);
                c += w[32] * cos(M_PI * (double)d);
                tab.C[bank * 4 + nn][d + 15] = (float)(c / 64.0);
            }
        }
    }

    dim3 grid(SPLIT, ROWS);
    fused_dwt_kernel<<<grid, 256>>>(signal, low, high, out, tab);
}

// round 17
// speedup vs baseline: 1.1129x; 1.0455x over previous
#include <cuda_runtime.h>
#include <math.h>
#include <stdint.h>

// Problem constants
#define SIG_LEN   131072
#define NW        4
#define ROWS      256
#define T_OUT     131166
#define SPLIT     4
#define CHK       32768               // input samples owned per block
#define SS        2048                // input samples per scan step

typedef unsigned long long ull;

// Host-computed constraint table: C[bank*4+n][d+15] includes the 1/64 factor.
struct FiltTab { float C[8][31]; };

// ---------------------------------------------------------------------------
__device__ __forceinline__ ull fma2(ull a, ull b, ull c) {
    ull d;
    asm("fma.rn.f32x2 %0, %1, %2, %3;" : "=l"(d) : "l"(a), "l"(b), "l"(c));
    return d;
}
__device__ __forceinline__ float hsum2(ull a) {
    float2 v = *reinterpret_cast<float2*>(&a);
    return v.x + v.y;
}

// Shared-memory arena (floats, DYNAMIC ~54.5 KB). Step phase: s_in0, s_in1,
// s_l1, s_a2. Tail: L3 overlays the staging region; L4/L5 overlay dead s_a2.
#define OFF_IN0 0      // 2080 floats
#define OFF_IN1 2080   // 2080 floats
#define OFF_L1  4160   // 1056 floats (15 carry + 1024)
#define OFF_A2  5216   // 8736 floats (l2 approx: chunk/4 + halo, +3 shift)
#define ARENA   13952  // 55808 bytes
// tail overlays
#define OFF_L3  0                  // 4256 floats (in staging region)
#define OFF_L4  OFF_A2             // 2144 floats (s_a2 dead after l3 pass)
#define OFF_L5  (OFF_A2 + 2144)    // 1088 floats
// filter scratch inside s_a2 (consumed into regs before step ~4 overwrites it)
#define SFILT   (OFF_A2 + 2000)

// ---------------------------------------------------------------------------
// Staging: s_in[i] = x[pin-15+i], i in [0, 2064). CHECK=false -> bare cp.async.
// ---------------------------------------------------------------------------
template<bool CHECK>
__device__ __forceinline__ void stage(uint32_t smb, const float* __restrict__ x,
                                      int off, int pin, int tid)
{
    #pragma unroll
    for (int c = 0; c < 9; c++) {
        int i = tid + 256 * c;
        if (c == 8 && tid >= 16) break;
        int gi = pin - 15 + i;
        uint32_t sa = smb + (uint32_t)(off + i) * 4u;
        if (CHECK) {
            bool ok = (gi >= 0) && (gi < SIG_LEN);
            const float* gp = x + (ok ? gi : 0);
            int sz = ok ? 4 : 0;
            asm volatile("cp.async.ca.shared.global [%0], [%1], 4, %2;"
                         :: "r"(sa), "l"(gp), "r"(sz) : "memory");
        } else {
            const float* gp = x + gi;
            asm volatile("cp.async.ca.shared.global [%0], [%1], 4;"
                         :: "r"(sa), "l"(gp) : "memory");
        }
    }
}

// ---------------------------------------------------------------------------
// Level-1 pass: 1024 outputs, 2/thread x 2 iters. Window q = src[2q..2q+17].
// ---------------------------------------------------------------------------
template<bool DET, bool MASK>
__device__ __forceinline__ void l1_pass(const float* __restrict__ src,
                                        float* __restrict__ dst,
                                        float* __restrict__ det, int hi,
                                        const ull* fa, const ull* fd, int tid)
{
    #pragma unroll
    for (int it = 0; it < 2; it++) {
        const int q = 2 * tid + 512 * it;
        const float* w = src + 2 * q;
        ulonglong2 v0 = *(const ulonglong2*)(w);
        ulonglong2 v1 = *(const ulonglong2*)(w + 4);
        ulonglong2 v2 = *(const ulonglong2*)(w + 8);
        ulonglong2 v3 = *(const ulonglong2*)(w + 12);
        ull p8 = *(const ull*)(w + 16);
        ull P[9] = {v0.x, v0.y, v1.x, v1.y, v2.x, v2.y, v3.x, v3.y, p8};
        ull a0 = 0ull, a1 = 0ull;
        #pragma unroll
        for (int m = 0; m < 8; m++) {
            a0 = fma2(fa[m], P[m],     a0);
            a1 = fma2(fa[m], P[m + 1], a1);
        }
        dst[15 + q] = hsum2(a0);
        dst[16 + q] = hsum2(a1);
        if (DET) {
            ull d0 = 0ull, d1 = 0ull;
            #pragma unroll
            for (int m = 0; m < 8; m++) {
                d0 = fma2(fd[m], P[m],     d0);
                d1 = fma2(fd[m], P[m + 1], d1);
            }
            float rd0 = hsum2(d0), rd1 = hsum2(d1);
            if (!MASK) {
                *reinterpret_cast<float2*>(det + q) = make_float2(rd0, rd1);
            } else {
                if (q < hi)     det[q]     = rd0;
                if (q + 1 < hi) det[q + 1] = rd1;
            }
        }
    }
}

// ---------------------------------------------------------------------------
// Level-2 pass: 512 outputs, 2/thread, one iter. Window q = src[2q..2q+17].
// ---------------------------------------------------------------------------
template<bool DET, bool MASK>
__device__ __forceinline__ void l2_pass(const float* __restrict__ src,
                                        float* __restrict__ a2,
                                        float* __restrict__ det,
                                        int hi, int dqlim,
                                        const ull* fa, const ull* fd, int tid)
{
    const int q = 2 * tid;
    const float* w = src + 2 * q;
    ulonglong2 v0 = *(const ulonglong2*)(w);
    ulonglong2 v1 = *(const ulonglong2*)(w + 4);
    ulonglong2 v2 = *(const ulonglong2*)(w + 8);
    ulonglong2 v3 = *(const ulonglong2*)(w + 12);
    ull p8 = *(const ull*)(w + 16);
    ull P[9] = {v0.x, v0.y, v1.x, v1.y, v2.x, v2.y, v3.x, v3.y, p8};
    ull a0 = 0ull, a1 = 0ull;
    #pragma unroll
    for (int m = 0; m < 8; m++) {
        a0 = fma2(fa[m], P[m],     a0);
        a1 = fma2(fa[m], P[m + 1], a1);
    }
    float ra0 = hsum2(a0), ra1 = hsum2(a1);
    if (!MASK) { a2[q] = ra0; a2[q + 1] = ra1; }
    else {
        if (q < dqlim)     a2[q]     = ra0;
        if (q + 1 < dqlim) a2[q + 1] = ra1;
    }
    if (DET) {
        ull d0 = 0ull, d1 = 0ull;
        #pragma unroll
        for (int m = 0; m < 8; m++) {
            d0 = fma2(fd[m], P[m],     d0);
            d1 = fma2(fd[m], P[m + 1], d1);
        }
        float rd0 = hsum2(d0), rd1 = hsum2(d1);
        if (!MASK) {
            *reinterpret_cast<float2*>(det + q) = make_float2(rd0, rd1);
        } else {
            if (q < hi)     det[q]     = rd0;
            if (q + 1 < hi) det[q + 1] = rd1;
        }
    }
}

// ---------------------------------------------------------------------------
// Fused constraint + 6-level DWT. Grid (SPLIT=4, ROWS), 256 threads, 4/SM.
// ---------------------------------------------------------------------------
__global__ void __launch_bounds__(256, 4)
fused_dwt_kernel(const float* __restrict__ signal,
                 const float* __restrict__ low,
                 const float* __restrict__ high,
                 float* __restrict__ out,
                 const FiltTab tab)
{
    extern __shared__ __align__(16) float sm[];
    const int tid = threadIdx.x;
    const int j   = blockIdx.x;
    const int r   = blockIdx.y;
    const int n   = r & 3;
    const float* x = signal + (size_t)(r >> 2) * SIG_LEN;
    float* orow = out + (size_t)r * T_OUT;

    uint32_t smb;
    asm("{ .reg .u64 t; cvta.to.shared.u64 t, %1; cvt.u32.u64 %0, t; }"
        : "=r"(smb) : "l"(sm));

    const int P0    = j * CHK - SS;
    const int nstep = (j == SPLIT - 1) ? 18 : 17;

    // Kick off step-0 staging FIRST (DRAM fetch overlaps prologue below)
    if (P0 >= 2048) stage<false>(smb, x, OFF_IN0, P0, tid);
    else            stage<true >(smb, x, OFF_IN0, P0, tid);
    asm volatile("cp.async.commit_group;" ::: "memory");

    // ---- Warp-0 filter constraint (no intermediate barriers) ----
    if (tid < 32) {
        const int bank = tid >> 4;
        const int jt   = tid & 15;
        const float* src = (bank ? high : low) + n * 16;
        const float* Cp  = tab.C[bank * 4 + n];
        float acc = 0.0f;
        #pragma unroll
        for (int k = 0; k < 16; k++)
            acc = fmaf(src[k], Cp[jt - k + 15], acc);
        float ss = acc * acc;
        #pragma unroll
        for (int m = 8; m >= 1; m >>= 1)
            ss += __shfl_xor_sync(0xffffffffu, ss, m);
        float nrm = sqrtf(ss);
        if (nrm < 1e-12f) nrm = 1e-12f;
        sm[SFILT + tid] = acc / nrm * 1.41421356237309515f;
    }

    // Init zeros: s_l1 tail (first carry source), s_a2 head pad + tail zeros
    if (tid < 15)               sm[OFF_L1 + 1024 + tid] = 0.f;
    if (tid >= 32 && tid < 35)  sm[OFF_A2 + (tid - 32)] = 0.f;
    if (tid >= 64 && tid < 81)  sm[OFF_A2 + 8719 + (tid - 64)] = 0.f;
    __syncthreads();                             // publish filters + zeros

    // Filters as packed f32x2 in registers (smem broadcast)
    ull fa[8], fd[8];
    {
        const ull* fp = (const ull*)(sm + SFILT);
        #pragma unroll
        for (int m = 0; m < 8; m++) { fa[m] = fp[m]; fd[m] = fp[m + 8]; }
    }

    const int Lout[6] = {65544, 32780, 16398, 8207, 4111, 2063};
    int olo[6], ohi[6];
    #pragma unroll
    for (int l = 0; l < 6; l++) {
        int c = CHK >> (l + 1);
        olo[l] = j * c;
        ohi[l] = (j == SPLIT - 1) ? Lout[l] : (j + 1) * c;
    }
    float* gd1 = orow + 65622;  float* gd2 = orow + 32842;
    float* gd3 = orow + 16444;  float* gd4 = orow + 8237;
    float* gd5 = orow + 4126;   float* gd6 = orow + 2063;

    // Generic masked 2-output level (tail levels 3..6)
    auto level = [&](const float* __restrict__ src, int woff,
                     float* __restrict__ dst, int dst0,
                     float* __restrict__ det, int tg0, int lo, int hi,
                     float* __restrict__ app, int nq)
    {
        for (int q = 2 * tid; q < nq; q += 512) {
            const float* w = src + woff + 2 * q;
            ulonglong2 v0 = *(const ulonglong2*)(w);
            ulonglong2 v1 = *(const ulonglong2*)(w + 4);
            ulonglong2 v2 = *(const ulonglong2*)(w + 8);
            ulonglong2 v3 = *(const ulonglong2*)(w + 12);
            ull p8 = *(const ull*)(w + 16);
            ull P[9] = {v0.x, v0.y, v1.x, v1.y, v2.x, v2.y, v3.x, v3.y, p8};
            ull a0 = 0ull, a1 = 0ull, d0 = 0ull, d1 = 0ull;
            #pragma unroll
            for (int m = 0; m < 8; m++) {
                a0 = fma2(fa[m], P[m],     a0);
                d0 = fma2(fd[m], P[m],     d0);
                a1 = fma2(fa[m], P[m + 1], a1);
                d1 = fma2(fd[m], P[m + 1], d1);
            }
            float ra0 = hsum2(a0), ra1 = hsum2(a1);
            float rd0 = hsum2(d0), rd1 = hsum2(d1);
            if (dst) { dst[dst0 + q] = ra0; dst[dst0 + q + 1] = ra1; }
            const int t = tg0 + q;
            if (t >= lo && t < hi)     { det[t]     = rd0; if (app) app[t]     = ra0; }
            if (t+1 >= lo && t+1 < hi) { det[t + 1] = rd1; if (app) app[t + 1] = ra1; }
        }
    };

    const int base2 = j * 8192 - 512;

    for (int step = 0; step < nstep; step++) {
        const int pin  = P0 + step * SS;
        const int cbuf = (step & 1) ? OFF_IN1 : OFF_IN0;
        const int nbuf = (step & 1) ? OFF_IN0 : OFF_IN1;
        __syncthreads();                         // prev L1/L2 reads done

        // Carry s_l1 head <- old tail; prefetch next step; wait current.
        if (tid < 15) sm[OFF_L1 + tid] = sm[OFF_L1 + 1024 + tid];
        if (step + 1 < nstep) {
            const int np = pin + SS;
            if (np >= 2048 && np < 129024) stage<false>(smb, x, nbuf, np, tid);
            else                           stage<true >(smb, x, nbuf, np, tid);
            asm volatile("cp.async.commit_group;" ::: "memory");
            asm volatile("cp.async.wait_group 1;" ::: "memory");
        } else {
            asm volatile("cp.async.wait_group 0;" ::: "memory");
        }
        __syncthreads();

        // Level 1: 1024 outputs at t = (pin>>1)+q; approx -> s_l1[15+q]
        float* d1p = gd1 + (pin >> 1);
        if (step == 0)
            l1_pass<false, false>(sm + cbuf, sm + OFF_L1, d1p, 0, fa, fd, tid);
        else if (step <= 16)
            l1_pass<true,  false>(sm + cbuf, sm + OFF_L1, d1p, 0, fa, fd, tid);
        else
            l1_pass<true,  true >(sm + cbuf, sm + OFF_L1, d1p,
                                  ohi[0] - (pin >> 1), fa, fd, tid);
        __syncthreads();

        // Level 2: 512 outputs at t = (pin>>2)+q; approx -> s_a2[step*512+3+q]
        float* a2d = sm + OFF_A2 + step * 512 + 3;
        float* d2p = gd2 + (pin >> 2);
        if (step == 0)
            l2_pass<false, false>(sm + OFF_L1, a2d, d2p, 0, 0, fa, fd, tid);
        else if (step <= 16)
            l2_pass<true,  false>(sm + OFF_L1, a2d, d2p, 0, 0, fa, fd, tid);
        else
            l2_pass<true,  true >(sm + OFF_L1, a2d, d2p,
                                  ohi[1] - (pin >> 2),
                                  Lout[1] - (base2 + step * 512), fa, fd, tid);
    }

    __syncthreads();
    // Zero L3 pads (head [0,3) and right-edge zeros [4225,4256))
    if (tid < 3)                sm[OFF_L3 + tid] = 0.f;
    if (tid >= 32 && tid < 63)  sm[OFF_L3 + 4225 + (tid - 32)] = 0.f;
    __syncthreads();

    // Tail: levels 3..6 once. Left halos 112/48/16 cover the dependency cone.
    {
        // Level 3: reads s_a2, writes L3 (staging region, dead)
        const int a3 = olo[2] - 112, n3 = ohi[2] - a3;      // even
        level(sm + OFF_A2, 276, sm + OFF_L3, 3,
              gd3, a3, olo[2], ohi[2], (float*)0, n3);
        __syncthreads();

        // Level 4: reads L3, writes L4 (s_a2 head, dead). Pad zeros merged
        // into this phase (disjoint from L4's written range [3, 2114)).
        if (tid < 3)                 sm[OFF_L4 + tid] = 0.f;
        if (tid >= 32 && tid < 62)   sm[OFF_L4 + 2114 + (tid - 32)] = 0.f;
        const int a4 = olo[3] - 48, n4 = ohi[3] - a4;
        level(sm + OFF_L3, 4, sm + OFF_L4, 3,
              gd4, a4, olo[3], ohi[3], (float*)0, n4);
        __syncthreads();

        // Level 5: reads L4, writes L5 (s_a2 + 2144, dead). Pads merged.
        if (tid < 3)                 sm[OFF_L5 + tid] = 0.f;
        if (tid >= 32 && tid < 62)   sm[OFF_L5 + 1058 + (tid - 32)] = 0.f;
        const int a5 = olo[4] - 16, n5 = ohi[4] - a5;
        level(sm + OFF_L4, 4, sm + OFF_L5, 3,
              gd5, a5, olo[4], ohi[4], (float*)0, n5);
        __syncthreads();

        // Level 6: reads L5, writes det6 + final approx
        level(sm + OFF_L5, 4, (float*)0, 0,
              gd6, olo[5], olo[5], ohi[5], orow, ohi[5] - olo[5]);
    }
}

// ---------------------------------------------------------------------------
extern "C" void kernel_launch(void* const* d_in, const int* in_sizes, int n_in,
                              void* d_out, int out_size) {
    const float* signal = (const float*)d_in[0];
    const float* low    = (const float*)d_in[1];
    const float* high   = (const float*)d_in[2];
    float* out = (float*)d_out;

    // Data-independent constraint table, computed on host (double precision):
    // C[d] = (1/64)(w0 + 2*sum_{f=1..31} w_f cos(pi f d/32) + w32 cos(pi d)),
    // w_f = exp(-(((f/32) - target)*4)^2), target = (n+0.5)/8 + bank/2.
    FiltTab tab;
    for (int bank = 0; bank < 2; bank++) {
        for (int nn = 0; nn < 4; nn++) {
            double target = ((double)nn + 0.5) / 8.0 + (bank ? 0.5 : 0.0);
            double w[33];
            for (int f = 0; f <= 32; f++) {
                double d = ((double)f / 32.0 - target) * 4.0;
                w[f] = exp(-d * d);
            }
            for (int d = -15; d <= 15; d++) {
                double c = w[0];
                for (int f = 1; f <= 31; f++)
                    c += 2.0 * w[f] * cos(M_PI * (double)(f * d) / 32.0);
                c += w[32] * cos(M_PI * (double)d);
                tab.C[bank * 4 + nn][d + 15] = (float)(c / 64.0);
            }
        }
    }

    cudaFuncSetAttribute(fused_dwt_kernel,
                         cudaFuncAttributeMaxDynamicSharedMemorySize,
                         ARENA * (int)sizeof(float));
    dim3 grid(SPLIT, ROWS);
    fused_dwt_kernel<<<grid, 256, ARENA * sizeof(float)>>>(
        signal, low, high, out, tab);
}